// round 2
// baseline (speedup 1.0000x reference)
#include <cuda_runtime.h>
#include <math.h>

#define TN 32768
#define CCH 256
#define NBATCH 64
#define NGN 512
#define NHH 4
#define DHD 64
#define MFEAT 266
#define MPAD 320
#define NEDGE 524288
#define NLAYER 5

// ------------------------- static device scratch -------------------------
__device__ float g_atoms[TN * CCH];
__device__ float g_h[TN * CCH];
__device__ float g_t1[TN * CCH];
__device__ float g_hbuf[TN * CCH];
__device__ float g_hloc[TN * CCH];
__device__ float g_q[TN * CCH];
__device__ float g_k[TN * CCH];
__device__ float g_v[TN * CCH];
__device__ float g_att[TN * CCH];
__device__ float g_obuf[TN * CCH];
__device__ float g_hatt[TN * CCH];
__device__ float g_out[TN * CCH];
__device__ float g_mbuf[TN * CCH];
__device__ float g_t2[(size_t)TN * 512];
__device__ float g_qp[(size_t)NBATCH * NHH * NGN * MPAD];
__device__ float g_kp[(size_t)NBATCH * NHH * NGN * MPAD];
__device__ float g_ctx[(size_t)NBATCH * NHH * MPAD * DHD];
__device__ float g_ksum[NBATCH * NHH * MPAD];
__device__ int g_cnt[TN];
__device__ int g_cur[TN];
__device__ int g_rowptr[TN + 1];
__device__ int g_eids[NEDGE];
__device__ int g_srcs[NEDGE];

// ------------------------- CSR build -------------------------
__global__ void zero_int_k() {
    int i = blockIdx.x * 256 + threadIdx.x;
    if (i < TN) { g_cnt[i] = 0; g_cur[i] = 0; }
}

__global__ void count_k(const int* __restrict__ dst) {
    int e = blockIdx.x * 256 + threadIdx.x;
    if (e < NEDGE) atomicAdd(&g_cnt[dst[e]], 1);
}

__global__ void scan_k() {  // 1 block, 1024 threads; TN = 1024*32
    __shared__ int part[1024];
    int t = threadIdx.x;
    int base = t * 32;
    int s = 0;
    for (int i = 0; i < 32; i++) s += g_cnt[base + i];
    part[t] = s;
    __syncthreads();
    for (int off = 1; off < 1024; off <<= 1) {
        int v = 0;
        if (t >= off) v = part[t - off];
        __syncthreads();
        part[t] += v;
        __syncthreads();
    }
    int run = (t == 0) ? 0 : part[t - 1];
    for (int i = 0; i < 32; i++) {
        g_rowptr[base + i] = run;
        run += g_cnt[base + i];
    }
    if (t == 1023) g_rowptr[TN] = part[1023];
}

__global__ void fill_k(const int* __restrict__ src, const int* __restrict__ dst) {
    int e = blockIdx.x * 256 + threadIdx.x;
    if (e < NEDGE) {
        int d = dst[e];
        int pos = atomicAdd(&g_cur[d], 1);
        int slot = g_rowptr[d] + pos;
        g_eids[slot] = e;
        g_srcs[slot] = src[e];
    }
}

// ------------------------- node init: atoms = log1p(x) @ node_w + node_b -------------------------
__global__ __launch_bounds__(256) void node_init_k(const float* __restrict__ x,
                                                   const float* __restrict__ nw,
                                                   const float* __restrict__ nb,
                                                   float* __restrict__ atoms) {
    int node = blockIdx.x * 4 + (threadIdx.x >> 6);
    int c4 = (threadIdx.x & 63) << 2;
    float4 acc = *(const float4*)&nb[c4];
#pragma unroll
    for (int i = 0; i < 11; i++) {
        float a = log1pf(x[node * 11 + i]);
        float4 w = *(const float4*)&nw[i * 256 + c4];
        acc.x += a * w.x; acc.y += a * w.y; acc.z += a * w.z; acc.w += a * w.w;
    }
    *(float4*)&atoms[(size_t)node * 256 + c4] = acc;
}

// ------------------------- aggregation: h = atoms + sum_in relu(atoms[src] + ea) -------------------------
__global__ __launch_bounds__(256) void agg_k(const float* __restrict__ atoms,
                                             const float* __restrict__ edge_attr,
                                             const float* __restrict__ ew,
                                             const float* __restrict__ eb,
                                             float* __restrict__ hout) {
    int node = blockIdx.x * 4 + (threadIdx.x >> 6);
    int c4 = (threadIdx.x & 63) << 2;
    float4 w0 = *(const float4*)&ew[0 * 256 + c4];
    float4 w1 = *(const float4*)&ew[1 * 256 + c4];
    float4 w2 = *(const float4*)&ew[2 * 256 + c4];
    float4 w3 = *(const float4*)&ew[3 * 256 + c4];
    float4 bb = *(const float4*)&eb[c4];
    int js = g_rowptr[node], je = g_rowptr[node + 1];
    float4 acc = make_float4(0.f, 0.f, 0.f, 0.f);
    for (int j = js; j < je; j++) {
        int sv = g_srcs[j];
        int e = g_eids[j];
        float t0 = edge_attr[e * 4 + 0], t1 = edge_attr[e * 4 + 1];
        float t2 = edge_attr[e * 4 + 2], t3 = edge_attr[e * 4 + 3];
        float4 a = *(const float4*)&atoms[(size_t)sv * 256 + c4];
        float mx = a.x + bb.x + t0 * w0.x + t1 * w1.x + t2 * w2.x + t3 * w3.x;
        float my = a.y + bb.y + t0 * w0.y + t1 * w1.y + t2 * w2.y + t3 * w3.y;
        float mz = a.z + bb.z + t0 * w0.z + t1 * w1.z + t2 * w2.z + t3 * w3.z;
        float mw = a.w + bb.w + t0 * w0.w + t1 * w1.w + t2 * w2.w + t3 * w3.w;
        acc.x += fmaxf(mx, 0.f); acc.y += fmaxf(my, 0.f);
        acc.z += fmaxf(mz, 0.f); acc.w += fmaxf(mw, 0.f);
    }
    float4 base = *(const float4*)&atoms[(size_t)node * 256 + c4];
    acc.x += base.x; acc.y += base.y; acc.z += base.z; acc.w += base.w;
    *(float4*)&hout[(size_t)node * 256 + c4] = acc;
}

// ------------------------- SGEMM: C[M,N] = A[M,K] @ B[K,N] (+bias)(+gelu) -------------------------
template <int GELU>
__global__ __launch_bounds__(256) void sgemm_k(const float* __restrict__ A,
                                               const float* __restrict__ B,
                                               const float* __restrict__ bias,
                                               float* __restrict__ C,
                                               int M, int N, int K) {
    __shared__ float As[8][132];
    __shared__ float Bs[8][128];
    const int tid = threadIdx.x;
    const int bm = blockIdx.y * 128;
    const int bn = blockIdx.x * 128;
    const int arow = tid >> 1;
    const int acol = (tid & 1) << 2;
    const int brow = tid >> 5;
    const int bcol = (tid & 31) << 2;
    const int ty = tid >> 4;
    const int tx = tid & 15;
    float acc[8][8];
#pragma unroll
    for (int i = 0; i < 8; i++)
#pragma unroll
        for (int j = 0; j < 8; j++) acc[i][j] = 0.f;
    const float* Aptr = A + (size_t)(bm + arow) * K + acol;
    const float* Bptr = B + (size_t)brow * N + bn + bcol;
    for (int k0 = 0; k0 < K; k0 += 8) {
        float4 av = *(const float4*)(Aptr + k0);
        float4 bv = *(const float4*)(Bptr + (size_t)k0 * N);
        As[acol + 0][arow] = av.x;
        As[acol + 1][arow] = av.y;
        As[acol + 2][arow] = av.z;
        As[acol + 3][arow] = av.w;
        *(float4*)&Bs[brow][bcol] = bv;
        __syncthreads();
#pragma unroll
        for (int kk = 0; kk < 8; kk++) {
            float af[8], bf[8];
            *(float4*)&af[0] = *(const float4*)&As[kk][ty * 8];
            *(float4*)&af[4] = *(const float4*)&As[kk][ty * 8 + 4];
            *(float4*)&bf[0] = *(const float4*)&Bs[kk][tx * 8];
            *(float4*)&bf[4] = *(const float4*)&Bs[kk][tx * 8 + 4];
#pragma unroll
            for (int i = 0; i < 8; i++)
#pragma unroll
                for (int j = 0; j < 8; j++) acc[i][j] += af[i] * bf[j];
        }
        __syncthreads();
    }
    float bb[8];
#pragma unroll
    for (int j = 0; j < 8; j++) bb[j] = bias ? bias[bn + tx * 8 + j] : 0.f;
#pragma unroll
    for (int i = 0; i < 8; i++) {
        size_t row = (size_t)(bm + ty * 8 + i) * N + bn + tx * 8;
#pragma unroll
        for (int j0 = 0; j0 < 8; j0 += 4) {
            float vv[4];
#pragma unroll
            for (int j = 0; j < 4; j++) {
                float t = acc[i][j0 + j] + bb[j0 + j];
                if (GELU) t = 0.5f * t * (1.f + erff(t * 0.70710678118654752f));
                vv[j] = t;
            }
            float4 v4 = make_float4(vv[0], vv[1], vv[2], vv[3]);
            *(float4*)&C[row + j0] = v4;
        }
    }
}

// ------------------------- LayerNorm(a + b) * g + beta, rows of 256 -------------------------
__global__ __launch_bounds__(256) void ln_k(const float* __restrict__ a,
                                            const float* __restrict__ b,
                                            const float* __restrict__ g,
                                            const float* __restrict__ be,
                                            float* __restrict__ outp) {
    int warp = threadIdx.x >> 5, lane = threadIdx.x & 31;
    size_t row = (size_t)(blockIdx.x * 8 + warp) * 256;
    float v[8];
#pragma unroll
    for (int j0 = 0; j0 < 8; j0 += 4) {
        float4 va = *(const float4*)&a[row + lane * 8 + j0];
        float4 vb = *(const float4*)&b[row + lane * 8 + j0];
        v[j0 + 0] = va.x + vb.x; v[j0 + 1] = va.y + vb.y;
        v[j0 + 2] = va.z + vb.z; v[j0 + 3] = va.w + vb.w;
    }
    float s = 0.f, sq = 0.f;
#pragma unroll
    for (int j = 0; j < 8; j++) { s += v[j]; sq += v[j] * v[j]; }
#pragma unroll
    for (int o = 16; o > 0; o >>= 1) {
        s += __shfl_xor_sync(0xFFFFFFFFu, s, o);
        sq += __shfl_xor_sync(0xFFFFFFFFu, sq, o);
    }
    float mean = s * (1.f / 256.f);
    float var = sq * (1.f / 256.f) - mean * mean;
    float rstd = rsqrtf(var + 1e-5f);
#pragma unroll
    for (int j0 = 0; j0 < 8; j0 += 4) {
        float4 vg = *(const float4*)&g[lane * 8 + j0];
        float4 vbe = *(const float4*)&be[lane * 8 + j0];
        float4 o4;
        o4.x = (v[j0 + 0] - mean) * rstd * vg.x + vbe.x;
        o4.y = (v[j0 + 1] - mean) * rstd * vg.y + vbe.y;
        o4.z = (v[j0 + 2] - mean) * rstd * vg.z + vbe.z;
        o4.w = (v[j0 + 3] - mean) * rstd * vg.w + vbe.w;
        *(float4*)&outp[row + lane * 8 + j0] = o4;
    }
}

__global__ __launch_bounds__(256) void add_k(const float* __restrict__ a,
                                             const float* __restrict__ b,
                                             float* __restrict__ c) {
    size_t i = ((size_t)blockIdx.x * 256 + threadIdx.x) * 4;
    float4 va = *(const float4*)&a[i];
    float4 vb = *(const float4*)&b[i];
    va.x += vb.x; va.y += vb.y; va.z += vb.z; va.w += vb.w;
    *(float4*)&c[i] = va;
}

// ------------------------- Performer features: qp = relu(q @ proj^T)+eps (pad m>=266 -> 0) -------------------------
__global__ __launch_bounds__(256) void perf_feat_k(const float* __restrict__ Qin,
                                                   const float* __restrict__ proj,
                                                   float* __restrict__ qp) {
    __shared__ float Qs[64][68];  // [d][n]
    __shared__ float Ps[64][68];  // [d][m]
    int mt = blockIdx.x;  // 0..4
    int nt = blockIdx.y;  // 0..7
    int bh = blockIdx.z;  // 0..255
    int b = bh >> 2, hh = bh & 3;
    int tid = threadIdx.x;
#pragma unroll
    for (int i = 0; i < 4; i++) {
        int idx = tid + i * 256;
        int rl = idx >> 4;
        int d4 = (idx & 15) << 2;
        float4 qv = *(const float4*)&Qin[(size_t)(b * 512 + nt * 64 + rl) * 256 + hh * 64 + d4];
        Qs[d4 + 0][rl] = qv.x; Qs[d4 + 1][rl] = qv.y;
        Qs[d4 + 2][rl] = qv.z; Qs[d4 + 3][rl] = qv.w;
        int mg = mt * 64 + rl;
        float4 pv = make_float4(0.f, 0.f, 0.f, 0.f);
        if (mg < MFEAT) pv = *(const float4*)&proj[(size_t)mg * 64 + d4];
        Ps[d4 + 0][rl] = pv.x; Ps[d4 + 1][rl] = pv.y;
        Ps[d4 + 2][rl] = pv.z; Ps[d4 + 3][rl] = pv.w;
    }
    __syncthreads();
    int ty = tid >> 4, tx = tid & 15;
    float acc[4][4];
#pragma unroll
    for (int i = 0; i < 4; i++)
#pragma unroll
        for (int j = 0; j < 4; j++) acc[i][j] = 0.f;
#pragma unroll 8
    for (int d = 0; d < 64; d++) {
        float af[4], bf[4];
        *(float4*)af = *(const float4*)&Qs[d][ty * 4];
        *(float4*)bf = *(const float4*)&Ps[d][tx * 4];
#pragma unroll
        for (int i = 0; i < 4; i++)
#pragma unroll
            for (int j = 0; j < 4; j++) acc[i][j] += af[i] * bf[j];
    }
#pragma unroll
    for (int i = 0; i < 4; i++) {
        size_t row = (size_t)(bh * 512 + nt * 64 + ty * 4 + i) * MPAD + mt * 64 + tx * 4;
        float vv[4];
#pragma unroll
        for (int j = 0; j < 4; j++) {
            int m = mt * 64 + tx * 4 + j;
            vv[j] = (m < MFEAT) ? (fmaxf(acc[i][j], 0.f) + 1e-3f) : 0.f;
        }
        *(float4*)&qp[row] = make_float4(vv[0], vv[1], vv[2], vv[3]);
    }
}

// ------------------------- Performer ctx: ctx[m,d] = sum_n kp[n,m] v[n,d]; ksum[m] = sum_n kp[n,m] -------------------------
__global__ __launch_bounds__(256) void perf_ctx_k(const float* __restrict__ kp,
                                                  const float* __restrict__ Vin,
                                                  float* __restrict__ ctx,
                                                  float* __restrict__ ksum) {
    __shared__ float Ks[64][64];  // [n][m]
    __shared__ float Vs[64][64];  // [n][d]
    int mt = blockIdx.x;  // 0..4
    int bh = blockIdx.y;
    int b = bh >> 2, hh = bh & 3;
    int tid = threadIdx.x;
    int ty = tid >> 4, tx = tid & 15;
    float acc[4][4];
#pragma unroll
    for (int i = 0; i < 4; i++)
#pragma unroll
        for (int j = 0; j < 4; j++) acc[i][j] = 0.f;
    float ksacc = 0.f;
    for (int n0 = 0; n0 < 512; n0 += 64) {
#pragma unroll
        for (int i = 0; i < 4; i++) {
            int idx = tid + i * 256;
            int rl = idx >> 4;
            int c4 = (idx & 15) << 2;
            *(float4*)&Ks[rl][c4] =
                *(const float4*)&kp[(size_t)(bh * 512 + n0 + rl) * MPAD + mt * 64 + c4];
            *(float4*)&Vs[rl][c4] =
                *(const float4*)&Vin[(size_t)(b * 512 + n0 + rl) * 256 + hh * 64 + c4];
        }
        __syncthreads();
        if (tid < 64) {
#pragma unroll 8
            for (int n = 0; n < 64; n++) ksacc += Ks[n][tid];
        }
#pragma unroll 8
        for (int n = 0; n < 64; n++) {
            float af[4], bf[4];
            *(float4*)af = *(const float4*)&Ks[n][ty * 4];
            *(float4*)bf = *(const float4*)&Vs[n][tx * 4];
#pragma unroll
            for (int i = 0; i < 4; i++)
#pragma unroll
                for (int j = 0; j < 4; j++) acc[i][j] += af[i] * bf[j];
        }
        __syncthreads();
    }
#pragma unroll
    for (int i = 0; i < 4; i++) {
        size_t row = (size_t)(bh * MPAD + mt * 64 + ty * 4 + i) * 64 + tx * 4;
        *(float4*)&ctx[row] = make_float4(acc[i][0], acc[i][1], acc[i][2], acc[i][3]);
    }
    if (tid < 64) ksum[bh * MPAD + mt * 64 + tid] = ksacc;
}

// ------------------------- Performer att: att[n,d] = (sum_m qp[n,m] ctx[m,d]) / (sum_m qp[n,m] ksum[m]) -------------------------
__global__ __launch_bounds__(256) void perf_att_k(const float* __restrict__ qp,
                                                  const float* __restrict__ ctx,
                                                  const float* __restrict__ ksum,
                                                  float* __restrict__ attout) {
    __shared__ float Qs[64][68];  // [m][n]
    __shared__ float Cs[64][64];  // [m][d]
    __shared__ float kss[64];
    __shared__ float dens[64];
    int nt = blockIdx.x;  // 0..7
    int bh = blockIdx.y;
    int b = bh >> 2, hh = bh & 3;
    int tid = threadIdx.x;
    int ty = tid >> 4, tx = tid & 15;
    float acc[4][4];
#pragma unroll
    for (int i = 0; i < 4; i++)
#pragma unroll
        for (int j = 0; j < 4; j++) acc[i][j] = 0.f;
    float dacc[4] = {0.f, 0.f, 0.f, 0.f};
    for (int m0 = 0; m0 < MPAD; m0 += 64) {
#pragma unroll
        for (int i = 0; i < 4; i++) {
            int idx = tid + i * 256;
            int rl = idx >> 4;
            int c4 = (idx & 15) << 2;
            float4 qv = *(const float4*)&qp[(size_t)(bh * 512 + nt * 64 + rl) * MPAD + m0 + c4];
            Qs[c4 + 0][rl] = qv.x; Qs[c4 + 1][rl] = qv.y;
            Qs[c4 + 2][rl] = qv.z; Qs[c4 + 3][rl] = qv.w;
            *(float4*)&Cs[rl][c4] = *(const float4*)&ctx[(size_t)(bh * MPAD + m0 + rl) * 64 + c4];
        }
        if (tid < 64) kss[tid] = ksum[bh * MPAD + m0 + tid];
        __syncthreads();
#pragma unroll 8
        for (int mm = 0; mm < 64; mm++) {
            float af[4], bf[4];
            *(float4*)af = *(const float4*)&Qs[mm][ty * 4];
            *(float4*)bf = *(const float4*)&Cs[mm][tx * 4];
#pragma unroll
            for (int i = 0; i < 4; i++)
#pragma unroll
                for (int j = 0; j < 4; j++) acc[i][j] += af[i] * bf[j];
            if (tx == 0) {
                float kv = kss[mm];
#pragma unroll
                for (int i = 0; i < 4; i++) dacc[i] += af[i] * kv;
            }
        }
        __syncthreads();
    }
    if (tx == 0) {
#pragma unroll
        for (int i = 0; i < 4; i++) dens[ty * 4 + i] = dacc[i];
    }
    __syncthreads();
#pragma unroll
    for (int i = 0; i < 4; i++) {
        float dinv = 1.f / dens[ty * 4 + i];
        size_t row = (size_t)(b * 512 + nt * 64 + ty * 4 + i) * 256 + hh * 64 + tx * 4;
        *(float4*)&attout[row] =
            make_float4(acc[i][0] * dinv, acc[i][1] * dinv, acc[i][2] * dinv, acc[i][3] * dinv);
    }
}

// ------------------------- global mean pool -------------------------
__global__ __launch_bounds__(256) void pool_k(const float* __restrict__ atoms,
                                              float* __restrict__ outp) {
    int b = blockIdx.x;
    int c = threadIdx.x;
    float s = 0.f;
    for (int n = 0; n < 512; n++) s += atoms[(size_t)(b * 512 + n) * 256 + c];
    outp[b * 256 + c] = s * (1.f / 512.f);
}

// ------------------------- host -------------------------
static float* symf(const void* s) {
    void* p = nullptr;
    cudaGetSymbolAddress(&p, s);
    return (float*)p;
}

extern "C" void kernel_launch(void* const* d_in, const int* in_sizes, int n_in,
                              void* d_out, int out_size) {
    const float* x = (const float*)d_in[0];
    const float* edge_attr = (const float*)d_in[1];
    const int* edge_index = (const int*)d_in[2];
    const float* node_w = (const float*)d_in[4];
    const float* node_b = (const float*)d_in[5];
    const float* edge_w = (const float*)d_in[6];
    const float* edge_b = (const float*)d_in[7];
    const float* gine_w1 = (const float*)d_in[8];
    const float* gine_b1 = (const float*)d_in[9];
    const float* gine_w2 = (const float*)d_in[10];
    const float* gine_b2 = (const float*)d_in[11];
    const float* q_w = (const float*)d_in[12];
    const float* k_w = (const float*)d_in[13];
    const float* v_w = (const float*)d_in[14];
    const float* o_w = (const float*)d_in[15];
    const float* o_b = (const float*)d_in[16];
    const float* proj = (const float*)d_in[17];
    const float* n1g = (const float*)d_in[18];
    const float* n1b = (const float*)d_in[19];
    const float* n2g = (const float*)d_in[20];
    const float* n2b = (const float*)d_in[21];
    const float* n3g = (const float*)d_in[22];
    const float* n3b = (const float*)d_in[23];
    const float* mw1 = (const float*)d_in[24];
    const float* mb1 = (const float*)d_in[25];
    const float* mw2 = (const float*)d_in[26];
    const float* mb2 = (const float*)d_in[27];
    float* outp = (float*)d_out;

    float* atoms = symf(g_atoms);
    float* h = symf(g_h);
    float* t1 = symf(g_t1);
    float* hbuf = symf(g_hbuf);
    float* hloc = symf(g_hloc);
    float* qb = symf(g_q);
    float* kb = symf(g_k);
    float* vb = symf(g_v);
    float* attb = symf(g_att);
    float* obuf = symf(g_obuf);
    float* hatt = symf(g_hatt);
    float* outb = symf(g_out);
    float* mbuf = symf(g_mbuf);
    float* t2 = symf(g_t2);
    float* qp = symf(g_qp);
    float* kp = symf(g_kp);
    float* ctx = symf(g_ctx);
    float* ksum = symf(g_ksum);

    const int* src = edge_index;
    const int* dst = edge_index + NEDGE;

    zero_int_k<<<TN / 256, 256>>>();
    count_k<<<NEDGE / 256, 256>>>(dst);
    scan_k<<<1, 1024>>>();
    fill_k<<<NEDGE / 256, 256>>>(src, dst);
    node_init_k<<<TN / 4, 256>>>(x, node_w, node_b, atoms);

    for (int l = 0; l < NLAYER; l++) {
        size_t wcc = (size_t)l * 256 * 256;
        agg_k<<<TN / 4, 256>>>(atoms, edge_attr, edge_w, edge_b, h);
        sgemm_k<1><<<dim3(2, 256), 256>>>(h, gine_w1 + wcc, gine_b1 + l * 256, t1, TN, 256, 256);
        sgemm_k<0><<<dim3(2, 256), 256>>>(t1, gine_w2 + wcc, gine_b2 + l * 256, hbuf, TN, 256, 256);
        ln_k<<<TN / 8, 256>>>(hbuf, atoms, n1g + l * 256, n1b + l * 256, hloc);
        sgemm_k<0><<<dim3(2, 256), 256>>>(atoms, q_w + wcc, nullptr, qb, TN, 256, 256);
        sgemm_k<0><<<dim3(2, 256), 256>>>(atoms, k_w + wcc, nullptr, kb, TN, 256, 256);
        sgemm_k<0><<<dim3(2, 256), 256>>>(atoms, v_w + wcc, nullptr, vb, TN, 256, 256);
        perf_feat_k<<<dim3(5, 8, 256), 256>>>(qb, proj + (size_t)l * MFEAT * 64, qp);
        perf_feat_k<<<dim3(5, 8, 256), 256>>>(kb, proj + (size_t)l * MFEAT * 64, kp);
        perf_ctx_k<<<dim3(5, 256), 256>>>(kp, vb, ctx, ksum);
        perf_att_k<<<dim3(8, 256), 256>>>(qp, ctx, ksum, attb);
        sgemm_k<0><<<dim3(2, 256), 256>>>(attb, o_w + wcc, o_b + l * 256, obuf, TN, 256, 256);
        ln_k<<<TN / 8, 256>>>(obuf, atoms, n2g + l * 256, n2b + l * 256, hatt);
        add_k<<<TN * 256 / 1024, 256>>>(hloc, hatt, outb);
        sgemm_k<1><<<dim3(4, 256), 256>>>(outb, mw1 + (size_t)l * 256 * 512, mb1 + l * 512, t2,
                                          TN, 512, 256);
        sgemm_k<0><<<dim3(2, 256), 256>>>(t2, mw2 + (size_t)l * 512 * 256, mb2 + l * 256, mbuf,
                                          TN, 256, 512);
        ln_k<<<TN / 8, 256>>>(outb, mbuf, n3g + l * 256, n3b + l * 256, atoms);
    }
    pool_k<<<NBATCH, 256>>>(atoms, outp);
}